// round 8
// baseline (speedup 1.0000x reference)
#include <cuda_runtime.h>
#include <cuda_bf16.h>
#include <cstdint>

// Problem constants
#define BB    32
#define DD    384
#define TTOT  4096
#define KK    256
#define TTILE 128
#define NTHR  512
#define KC    64
#define NCHK  6
#define TAU   1e-2f
#define MAXF  32768
#define NPART 1024

#define Q_ELEMS   ((size_t)BB * DD * TTOT)
#define IDX_ELEMS ((size_t)BB * TTOT)

// SMEM layout (bytes)
#define A_OFF     0                  // z bf16 hi(16K)+lo(16K), rows=t(128), 128B, swizzled
#define B_OFF     32768              // cb bf16 hi(32K)+lo(32K), rows=k, 128B, swizzled
#define ZF_OFF    98304              // fp32 bounce [64][132] = 33792
#define ES_OFF    132096             // e2 [256] f32
#define REDV_OFF  133120             // [128][4] f32
#define REDK_OFF  135168             // [128][4] i32
#define BV_OFF    137216             // [128] f32
#define BK_OFF    137728             // [128] i32
#define CC_OFF    138240             // [128] i32
#define CL_OFF    138752             // [128][7] i32
#define LRED_OFF  142336             // [512] f32
#define SMEM_SZ   144384             // occ 1 @ 512 thr

// Scratch
__device__ float  g_ct[DD * KK];
__device__ float  g_e2f[KK];
__device__ int    g_idx[BB * TTOT];
__device__ float  g_partials[NPART];
__device__ int    g_nflag;
__device__ int    g_fpt[MAXF];
__device__ int    g_fcnt[MAXF];
__device__ int    g_fold[MAXF];
__device__ int    g_fcand[MAXF][8];
__device__ float  g_ldelta[MAXF];
__device__ unsigned short g_bswh[NCHK * KK * KC];  // pre-swizzled bf16 codebook hi
__device__ unsigned short g_bswl[NCHK * KK * KC];  // lo

static __device__ __forceinline__ uint32_t smem_u32(const void* p) {
    uint32_t a;
    asm("{ .reg .u64 t; cvta.to.shared.u64 t, %1; cvt.u32.u64 %0, t; }"
        : "=r"(a) : "l"(p));
    return a;
}

#define CPASYNC16(dst, src) \
    asm volatile("cp.async.cg.shared.global [%0], [%1], 16;" \
        :: "r"(dst), "l"(src) : "memory")
#define CPCOMMIT  asm volatile("cp.async.commit_group;" ::: "memory")
#define CPWAIT0   asm volatile("cp.async.wait_group 0;" ::: "memory")

#define LDSM4(r, ad) \
    asm volatile("ldmatrix.sync.aligned.m8n8.x4.shared.b16 {%0,%1,%2,%3}, [%4];" \
        : "=r"((r)[0]), "=r"((r)[1]), "=r"((r)[2]), "=r"((r)[3]) : "r"(ad))

#define MMA16816(d, a, b0, b1) \
    asm volatile("mma.sync.aligned.m16n8k16.row.col.f32.bf16.bf16.f32 " \
        "{%0,%1,%2,%3},{%4,%5,%6,%7},{%8,%9},{%0,%1,%2,%3};" \
        : "+f"((d)[0]), "+f"((d)[1]), "+f"((d)[2]), "+f"((d)[3]) \
        : "r"((a)[0]), "r"((a)[1]), "r"((a)[2]), "r"((a)[3]), "r"(b0), "r"(b1))

// ---- prep: g_ct transpose + XLA-emulated e2 + bf16 split/swizzle codebook + reset ----
__global__ void vq_prep(const float* __restrict__ cb) {
    const unsigned FULL = 0xffffffffu;
    int bid = blockIdx.x;
    if (bid < 384) {
        int gid = bid * 256 + threadIdx.x;
        int k = gid / DD;
        int d = gid - k * DD;
        g_ct[d * KK + k] = cb[gid];
    } else if (bid < 416) {
        int lane = threadIdx.x & 31;
        int warp = threadIdx.x >> 5;
        int row = (bid - 384) * 8 + warp;
        const float* c = cb + (size_t)row * DD;
        float s = 0.f;
#pragma unroll
        for (int j = 0; j < DD / 32; ++j) {
            float v = c[lane + 32 * j];
            s = fmaf(v, v, s);
        }
#pragma unroll
        for (int off = 16; off; off >>= 1) s += __shfl_down_sync(FULL, s, off);
        if (lane == 0) g_e2f[row] = s;
    } else if (bid < 800) {
        int gid = (bid - 416) * 256 + threadIdx.x;   // < 98304
        int k = gid / DD;
        int d = gid - k * DD;
        float x = cb[gid];
        __nv_bfloat16 h = __float2bfloat16(x);
        __nv_bfloat16 l = __float2bfloat16(x - __bfloat162float(h));
        int c   = d >> 6;
        int din = d & 63;
        int idx16 = c * (KK * KC) + k * KC
                  + ((((unsigned)(din * 2)) ^ ((unsigned)(k & 7) * 16)) >> 1);
        g_bswh[idx16] = __bfloat16_as_ushort(h);
        g_bswl[idx16] = __bfloat16_as_ushort(l);
    } else {
        if (threadIdx.x == 0) g_nflag = 0;
    }
}

// ---- main: mma.sync bf16-split screening + argmin + flags + loss ----
__global__ __launch_bounds__(NTHR, 1) void vq_main(const float* __restrict__ z) {
    extern __shared__ char smem[];
    const uint32_t sb = smem_u32(smem);
    const int tid  = threadIdx.x;
    const int lane = tid & 31;
    const int w    = tid >> 5;
    const int wm   = w & 3;    // t slice (32 t)
    const int wn   = w >> 2;   // code slice (64 codes)
    const int b    = blockIdx.y;
    const int tg   = blockIdx.x * TTILE;

    if (tid < KK) ((float*)(smem + ES_OFF))[tid] = g_e2f[tid];

    const float* zb = z + (size_t)b * DD * TTOT + tg;
    float* zf = (float*)(smem + ZF_OFF);

    float acc[2][8][4];   // [mi][n8 tile][frag]
#pragma unroll
    for (int i = 0; i < 2; ++i)
#pragma unroll
        for (int j = 0; j < 8; ++j)
#pragma unroll
            for (int q = 0; q < 4; ++q) acc[i][j][q] = 0.f;

    float x2acc = 0.f;

    for (int c = 0; c < NCHK; ++c) {
        __syncthreads();   // prev MMA done reading A/B; buffers free
        // stage codebook chunk (pre-swizzled) hi+lo via cp.async: 64KB
        {
            const char* sh = (const char*)(g_bswh + c * (KK * KC));
            const char* sl = (const char*)(g_bswl + c * (KK * KC));
            uint32_t dh = sb + B_OFF + (unsigned)tid * 16;
            uint32_t dl = sb + B_OFF + 32768 + (unsigned)tid * 16;
#pragma unroll
            for (int j = 0; j < 4; ++j) {
                CPASYNC16(dh + 8192u * j, sh + (tid + NTHR * j) * 16);
                CPASYNC16(dl + 8192u * j, sl + (tid + NTHR * j) * 16);
            }
        }
        // z chunk (64 d x 128 t) -> fp32 bounce via cp.async (coalesced along t)
#pragma unroll
        for (int p = 0; p < 4; ++p) {
            int d  = p * 16 + (tid >> 5);
            int t4 = tid & 31;
            CPASYNC16(sb + ZF_OFF + (unsigned)(d * 132 + t4 * 4) * 4,
                      zb + (size_t)(c * KC + d) * TTOT + t4 * 4);
        }
        CPCOMMIT;
        CPWAIT0;
        __syncthreads();
        // repack: bounce -> A tile (rows=t(128), bf16 hi/lo pairs along d, swizzled) + x2
        {
            int t  = tid & 127;
            int dg = tid >> 7;   // 0..3, 16 d each
#pragma unroll
            for (int j = 0; j < 8; ++j) {
                int d0 = dg * 16 + j * 2;
                float f0 = zf[d0 * 132 + t];
                float f1 = zf[(d0 + 1) * 132 + t];
                x2acc = fmaf(f0, f0, fmaf(f1, f1, x2acc));
                __nv_bfloat16 h0 = __float2bfloat16(f0), h1 = __float2bfloat16(f1);
                __nv_bfloat16 l0 = __float2bfloat16(f0 - __bfloat162float(h0));
                __nv_bfloat16 l1 = __float2bfloat16(f1 - __bfloat162float(h1));
                unsigned hw = ((unsigned)__bfloat16_as_ushort(h1) << 16) | __bfloat16_as_ushort(h0);
                unsigned lw = ((unsigned)__bfloat16_as_ushort(l1) << 16) | __bfloat16_as_ushort(l0);
                unsigned off = (unsigned)t * 128 + (((unsigned)(d0 * 2)) ^ ((unsigned)(t & 7) * 16));
                *(unsigned*)(smem + A_OFF + off) = hw;
                *(unsigned*)(smem + A_OFF + 16384 + off) = lw;
            }
        }
        __syncthreads();

        // MMA: 4 k16 steps over this 64-d chunk, 3-term split
#pragma unroll
        for (int ks = 0; ks < 4; ++ks) {
            uint32_t ah[2][4], al[2][4];
#pragma unroll
            for (int mi = 0; mi < 2; ++mi) {
                int row = wm * 32 + mi * 16 + ((lane >> 3) & 1) * 8 + (lane & 7);
                unsigned kb = (unsigned)ks * 32 + ((lane >> 4) & 1) * 16;
                uint32_t ad = sb + A_OFF + (unsigned)row * 128 + (kb ^ ((unsigned)(row & 7) * 16));
                LDSM4(ah[mi], ad);
                LDSM4(al[mi], ad + 16384);
            }
#pragma unroll
            for (int ng = 0; ng < 4; ++ng) {
                int n = wn * 64 + ng * 16 + ((lane >> 4) & 1) * 8 + (lane & 7);
                unsigned kb = (unsigned)ks * 32 + ((lane >> 3) & 1) * 16;
                uint32_t bd = sb + B_OFF + (unsigned)n * 128 + (kb ^ ((unsigned)(n & 7) * 16));
                uint32_t bh[4], bl[4];
                LDSM4(bh, bd);
                LDSM4(bl, bd + 32768);
#pragma unroll
                for (int mi = 0; mi < 2; ++mi) {
#pragma unroll
                    for (int tile = 0; tile < 2; ++tile) {
                        float* dst = acc[mi][ng * 2 + tile];
                        MMA16816(dst, ah[mi], bh[tile * 2], bh[tile * 2 + 1]);
                        MMA16816(dst, al[mi], bh[tile * 2], bh[tile * 2 + 1]);
                        MMA16816(dst, ah[mi], bl[tile * 2], bl[tile * 2 + 1]);
                    }
                }
            }
        }
    }

    // ---- epilogue: argmin over 256 codes ----
    const float* es = (const float*)(smem + ES_OFF);
    float* redv = (float*)(smem + REDV_OFF);
    int*   redk = (int*)(smem + REDK_OFF);
    float* bestv_s = (float*)(smem + BV_OFF);
    int*   bestk_s = (int*)(smem + BK_OFF);
    int*   ccnt = (int*)(smem + CC_OFF);
    int*   clst = (int*)(smem + CL_OFF);
    float* lred = (float*)(smem + LRED_OFF);

    // thread-local best per t-row j: j = mi*2 + (frag>>1)
    float bv[4];
    int   bk[4];
#pragma unroll
    for (int j = 0; j < 4; ++j) { bv[j] = 3.4e38f; bk[j] = KK; }
#pragma unroll
    for (int mi = 0; mi < 2; ++mi)
#pragma unroll
        for (int nt = 0; nt < 8; ++nt)
#pragma unroll
            for (int ci = 0; ci < 4; ++ci) {
                int code = wn * 64 + nt * 8 + (lane & 3) * 2 + (ci & 1);
                int j = mi * 2 + (ci >> 1);
                float sc = es[code] - 2.0f * acc[mi][nt][ci];
                if (sc < bv[j] || (sc == bv[j] && code < bk[j])) { bv[j] = sc; bk[j] = code; }
            }
    const unsigned FULL = 0xffffffffu;
#pragma unroll
    for (int j = 0; j < 4; ++j) {
#pragma unroll
        for (int off = 1; off < 4; off <<= 1) {
            float ov = __shfl_xor_sync(FULL, bv[j], off);
            int   ok = __shfl_xor_sync(FULL, bk[j], off);
            if (ov < bv[j] || (ov == bv[j] && ok < bk[j])) { bv[j] = ov; bk[j] = ok; }
        }
    }
    if ((lane & 3) == 0) {
#pragma unroll
        for (int j = 0; j < 4; ++j) {
            int t = wm * 32 + (j >> 1) * 16 + (lane >> 2) + (j & 1) * 8;
            redv[t * 4 + wn] = bv[j];
            redk[t * 4 + wn] = bk[j];
        }
    }
    __syncthreads();
    if (tid < TTILE) {
        float fv = redv[tid * 4];
        int   fk = redk[tid * 4];
#pragma unroll
        for (int q = 1; q < 4; ++q) {
            float v = redv[tid * 4 + q];
            int   k = redk[tid * 4 + q];
            if (v < fv || (v == fv && k < fk)) { fv = v; fk = k; }
        }
        bestv_s[tid] = fv;
        bestk_s[tid] = fk;
        ccnt[tid] = 0;
        g_idx[b * TTOT + tg + tid] = fk;
    }
    __syncthreads();

    // candidate scan (score <= best + TAU, code != best)
#pragma unroll
    for (int mi = 0; mi < 2; ++mi)
#pragma unroll
        for (int nt = 0; nt < 8; ++nt)
#pragma unroll
            for (int ci = 0; ci < 4; ++ci) {
                int code = wn * 64 + nt * 8 + (lane & 3) * 2 + (ci & 1);
                int t = wm * 32 + mi * 16 + (lane >> 2) + ((ci >> 1) ? 8 : 0);
                float sc = es[code] - 2.0f * acc[mi][nt][ci];
                if (sc <= bestv_s[t] + TAU && code != bestk_s[t]) {
                    int slot = atomicAdd(&ccnt[t], 1);
                    if (slot < 7) clst[t * 7 + slot] = code;
                }
            }
    __syncthreads();

    if (tid < TTILE && ccnt[tid] > 0) {
        int slot = atomicAdd(&g_nflag, 1);
        if (slot < MAXF) {
            g_fpt[slot] = (b << 12) | (tg + tid);
            g_fold[slot] = bestk_s[tid];
            int cnum = ccnt[tid];
            if (cnum <= 7) {
                g_fcand[slot][0] = bestk_s[tid];
#pragma unroll
                for (int j = 0; j < 7; ++j)
                    if (j < cnum) g_fcand[slot][1 + j] = clst[tid * 7 + j];
                g_fcnt[slot] = cnum + 1;
            } else {
                g_fcnt[slot] = -1;   // scan all 256
            }
        }
    }

    // loss partial: sum x2 + sum best scores
    lred[tid] = x2acc + ((tid < TTILE) ? bestv_s[tid] : 0.f);
    __syncthreads();
    for (int s = NTHR / 2; s > 0; s >>= 1) {
        if (tid < s) lred[tid] += lred[tid + s];
        __syncthreads();
    }
    if (tid == 0) g_partials[b * gridDim.x + blockIdx.x] = lred[0];
}

// ---- refine: reference-fp32-EMULATED re-decision of flagged points ----
__global__ void vq_refine(const float* __restrict__ z, const float* __restrict__ cb) {
    const unsigned FULL = 0xffffffffu;
    __shared__ float zsh[4][DD];
    const int lane = threadIdx.x & 31;
    const int warp = threadIdx.x >> 5;
    const int warps_total = gridDim.x * (blockDim.x >> 5);
    const int wg = blockIdx.x * (blockDim.x >> 5) + warp;

    int n = g_nflag;
    if (n > MAXF) n = MAXF;

    for (int e = wg; e < n; e += warps_total) {
        const int pt = g_fpt[e];
        const int b = pt >> 12;
        const int t = pt & 4095;
        const int kold = g_fold[e];
        const float* zp = z + (size_t)b * DD * TTOT + t;

        for (int d = lane; d < DD; d += 32) zsh[warp][d] = zp[(size_t)d * TTOT];
        __syncwarp();

        float s = 0.f;
#pragma unroll
        for (int j = 0; j < DD / 32; ++j) {
            float v = zsh[warp][lane + 32 * j];
            s = fmaf(v, v, s);
        }
#pragma unroll
        for (int off = 16; off; off >>= 1) s += __shfl_down_sync(FULL, s, off);
        const float x2f = __shfl_sync(FULL, s, 0);

        const int cnt = g_fcnt[e];
        const int ncand = (cnt < 0) ? KK : cnt;

        float bestdf = 3.4e38f;
        int bestk = 1 << 30;
        float dfold_l = 0.f;
        for (int c = lane; c < ncand; c += 32) {
            const int k = (cnt < 0) ? c : g_fcand[e][c];
            const float* ck = cb + (size_t)k * DD;
            float dot = 0.f;
#pragma unroll 8
            for (int d = 0; d < DD; ++d) dot = fmaf(zsh[warp][d], ck[d], dot);
            float df = __fadd_rn(__fsub_rn(x2f, 2.0f * dot), g_e2f[k]);
            if (df < bestdf || (df == bestdf && k < bestk)) { bestdf = df; bestk = k; }
            if (k == kold) dfold_l = df;
        }
#pragma unroll
        for (int off = 16; off; off >>= 1) {
            float od = __shfl_down_sync(FULL, bestdf, off);
            int   ok = __shfl_down_sync(FULL, bestk, off);
            float oo = __shfl_down_sync(FULL, dfold_l, off);
            if (od < bestdf || (od == bestdf && ok < bestk)) { bestdf = od; bestk = ok; }
            dfold_l += oo;
        }
        if (lane == 0) {
            g_idx[b * TTOT + t] = bestk;
            g_ldelta[e] = bestdf - dfold_l;
        }
        __syncwarp();
    }
}

// ---- writer: gather-only quantize + indices ----
__global__ __launch_bounds__(256) void vq_write(float* __restrict__ out) {
    const int tid = threadIdx.x;
    const int b  = blockIdx.y;
    const int dz = blockIdx.z;
    const int t4 = (blockIdx.x * 256 + tid) << 2;

    const int4 kk = *(const int4*)&g_idx[b * TTOT + t4];

    if (dz == 0) {
        float4 fi = make_float4((float)kk.x, (float)kk.y, (float)kk.z, (float)kk.w);
        *(float4*)&out[Q_ELEMS + (size_t)b * TTOT + t4] = fi;
    }

    float* ob = out + (size_t)b * DD * TTOT + t4;
    const int dlo = dz * (DD / 4);
#pragma unroll 4
    for (int d = dlo; d < dlo + DD / 4; ++d) {
        const float* row = g_ct + d * KK;
        float4 q = make_float4(row[kk.x], row[kk.y], row[kk.z], row[kk.w]);
        *(float4*)&ob[(size_t)d * TTOT] = q;
    }
}

// ---- finalize ----
__global__ void vq_finalize(float* __restrict__ out) {
    __shared__ float s[256];
    int n = g_nflag;
    if (n > MAXF) n = MAXF;
    float a = 0.f;
    for (int j = threadIdx.x; j < NPART; j += 256) a += g_partials[j];
    for (int e = threadIdx.x; e < n; e += 256) a += g_ldelta[e];
    s[threadIdx.x] = a;
    __syncthreads();
    for (int st = 128; st > 0; st >>= 1) {
        if (threadIdx.x < st) s[threadIdx.x] += s[threadIdx.x + st];
        __syncthreads();
    }
    if (threadIdx.x == 0)
        out[Q_ELEMS + IDX_ELEMS] =
            0.25f * s[0] / (float)((size_t)BB * TTOT * DD);
}

extern "C" void kernel_launch(void* const* d_in, const int* in_sizes, int n_in,
                              void* d_out, int out_size) {
    const float* z  = (const float*)d_in[0];
    const float* cb = (const float*)d_in[1];
    float* out = (float*)d_out;

    cudaFuncSetAttribute(vq_main, cudaFuncAttributeMaxDynamicSharedMemorySize, SMEM_SZ);

    vq_prep<<<801, 256>>>(cb);
    dim3 grid(TTOT / TTILE, BB);
    vq_main<<<grid, NTHR, SMEM_SZ>>>(z);
    vq_refine<<<64, 128>>>(z, cb);
    dim3 wgrid(TTOT / 1024, BB, 4);
    vq_write<<<wgrid, 256>>>(out);
    vq_finalize<<<1, 256>>>(out);
}

// round 9
// speedup vs baseline: 1.1064x; 1.1064x over previous
#include <cuda_runtime.h>
#include <cuda_bf16.h>
#include <cstdint>

// Problem constants
#define BB    32
#define DD    384
#define TTOT  4096
#define KK    256
#define TTILE 128
#define NTHR  512
#define KC    64
#define NCHK  6
#define TAU   1e-2f
#define MAXF  32768
#define NPART 1024

#define Q_ELEMS   ((size_t)BB * DD * TTOT)
#define IDX_ELEMS ((size_t)BB * TTOT)

// SMEM layout (bytes)
#define A_OFF     0                  // z bf16 hi(16K)+lo(16K), rows=t(128), 128B, swizzled
#define B0_OFF    32768              // B buffer 0: hi 32K + lo 32K
#define B1_OFF    98304              // B buffer 1: hi 32K + lo 32K
#define ZF_OFF    163840             // fp32 bounce [64][132] = 33792
#define ES_OFF    197632             // e2 [256] f32
#define REDV_OFF  198656             // [128][4] f32
#define REDK_OFF  200704             // [128][4] i32
#define BV_OFF    202752             // [128] f32
#define BK_OFF    203264             // [128] i32
#define CC_OFF    203776             // [128] i32
#define CL_OFF    204288             // [128][7] i32
#define LRED_OFF  207872             // [512] f32
#define SMEM_SZ   209920             // ~205KB, occ 1 @ 512 thr

// Scratch
__device__ float  g_ct[DD * KK];
__device__ float  g_e2f[KK];
__device__ int    g_idx[BB * TTOT];
__device__ float  g_partials[NPART];
__device__ int    g_nflag;
__device__ int    g_fpt[MAXF];
__device__ int    g_fcnt[MAXF];
__device__ int    g_fold[MAXF];
__device__ int    g_fcand[MAXF][8];
__device__ float  g_ldelta[MAXF];
__device__ unsigned short g_bswh[NCHK * KK * KC];  // pre-swizzled bf16 codebook hi
__device__ unsigned short g_bswl[NCHK * KK * KC];  // lo

static __device__ __forceinline__ uint32_t smem_u32(const void* p) {
    uint32_t a;
    asm("{ .reg .u64 t; cvta.to.shared.u64 t, %1; cvt.u32.u64 %0, t; }"
        : "=r"(a) : "l"(p));
    return a;
}

#define CPASYNC16(dst, src) \
    asm volatile("cp.async.cg.shared.global [%0], [%1], 16;" \
        :: "r"(dst), "l"(src) : "memory")
#define CPCOMMIT  asm volatile("cp.async.commit_group;" ::: "memory")
#define CPWAIT0   asm volatile("cp.async.wait_group 0;" ::: "memory")

#define LDSM4(r, ad) \
    asm volatile("ldmatrix.sync.aligned.m8n8.x4.shared.b16 {%0,%1,%2,%3}, [%4];" \
        : "=r"((r)[0]), "=r"((r)[1]), "=r"((r)[2]), "=r"((r)[3]) : "r"(ad))

#define MMA16816(d, a, b0, b1) \
    asm volatile("mma.sync.aligned.m16n8k16.row.col.f32.bf16.bf16.f32 " \
        "{%0,%1,%2,%3},{%4,%5,%6,%7},{%8,%9},{%0,%1,%2,%3};" \
        : "+f"((d)[0]), "+f"((d)[1]), "+f"((d)[2]), "+f"((d)[3]) \
        : "r"((a)[0]), "r"((a)[1]), "r"((a)[2]), "r"((a)[3]), "r"(b0), "r"(b1))

// ---- prep: g_ct transpose + XLA-emulated e2 + bf16 split/swizzle codebook + reset ----
__global__ void vq_prep(const float* __restrict__ cb) {
    const unsigned FULL = 0xffffffffu;
    int bid = blockIdx.x;
    if (bid < 384) {
        int gid = bid * 256 + threadIdx.x;
        int k = gid / DD;
        int d = gid - k * DD;
        g_ct[d * KK + k] = cb[gid];
    } else if (bid < 416) {
        int lane = threadIdx.x & 31;
        int warp = threadIdx.x >> 5;
        int row = (bid - 384) * 8 + warp;
        const float* c = cb + (size_t)row * DD;
        float s = 0.f;
#pragma unroll
        for (int j = 0; j < DD / 32; ++j) {
            float v = c[lane + 32 * j];
            s = fmaf(v, v, s);
        }
#pragma unroll
        for (int off = 16; off; off >>= 1) s += __shfl_down_sync(FULL, s, off);
        if (lane == 0) g_e2f[row] = s;
    } else if (bid < 800) {
        int gid = (bid - 416) * 256 + threadIdx.x;   // < 98304
        int k = gid / DD;
        int d = gid - k * DD;
        float x = cb[gid];
        __nv_bfloat16 h = __float2bfloat16(x);
        __nv_bfloat16 l = __float2bfloat16(x - __bfloat162float(h));
        int c   = d >> 6;
        int din = d & 63;
        int idx16 = c * (KK * KC) + k * KC
                  + ((((unsigned)(din * 2)) ^ ((unsigned)(k & 7) * 16)) >> 1);
        g_bswh[idx16] = __bfloat16_as_ushort(h);
        g_bswl[idx16] = __bfloat16_as_ushort(l);
    } else {
        if (threadIdx.x == 0) g_nflag = 0;
    }
}

// ---- main: mma.sync bf16-split screening, 2-stage cp.async pipeline ----
__global__ __launch_bounds__(NTHR, 1) void vq_main(const float* __restrict__ z) {
    extern __shared__ char smem[];
    const uint32_t sb = smem_u32(smem);
    const int tid  = threadIdx.x;
    const int lane = tid & 31;
    const int w    = tid >> 5;
    const int wm   = w & 3;    // t slice (32 t)
    const int wn   = w >> 2;   // code slice (64 codes)
    const int b    = blockIdx.y;
    const int tg   = blockIdx.x * TTILE;

    if (tid < KK) ((float*)(smem + ES_OFF))[tid] = g_e2f[tid];

    const float* zb = z + (size_t)b * DD * TTOT + tg;
    float* zf = (float*)(smem + ZF_OFF);

    float acc[2][8][4];   // [mi][n8 tile][frag]
#pragma unroll
    for (int i = 0; i < 2; ++i)
#pragma unroll
        for (int j = 0; j < 8; ++j)
#pragma unroll
            for (int q = 0; q < 4; ++q) acc[i][j][q] = 0.f;

    float x2acc = 0.f;

    // staging helpers (inline): B chunk c -> buffer base bb; zf chunk c
    const uint32_t bbase[2] = { sb + B0_OFF, sb + B1_OFF };

    // prologue: stage chunk 0
    {
        const char* sh = (const char*)(g_bswh);
        const char* sl = (const char*)(g_bswl);
        uint32_t dh = bbase[0] + (unsigned)tid * 16;
        uint32_t dl = bbase[0] + 32768 + (unsigned)tid * 16;
#pragma unroll
        for (int j = 0; j < 4; ++j) {
            CPASYNC16(dh + 8192u * j, sh + (tid + NTHR * j) * 16);
            CPASYNC16(dl + 8192u * j, sl + (tid + NTHR * j) * 16);
        }
#pragma unroll
        for (int p = 0; p < 4; ++p) {
            int d  = p * 16 + (tid >> 5);
            int t4 = tid & 31;
            CPASYNC16(sb + ZF_OFF + (unsigned)(d * 132 + t4 * 4) * 4,
                      zb + (size_t)d * TTOT + t4 * 4);
        }
        CPCOMMIT;
    }

    for (int c = 0; c < NCHK; ++c) {
        CPWAIT0;            // chunk c staging complete
        __syncthreads();    // + all warps done with MMA(c-1) (A, B free)

        // repack: bounce -> A tile (rows=t(128), bf16 hi/lo pairs along d, swizzled) + x2
        {
            int t  = tid & 127;
            int dg = tid >> 7;   // 0..3, 16 d each
#pragma unroll
            for (int j = 0; j < 8; ++j) {
                int d0 = dg * 16 + j * 2;
                float f0 = zf[d0 * 132 + t];
                float f1 = zf[(d0 + 1) * 132 + t];
                x2acc = fmaf(f0, f0, fmaf(f1, f1, x2acc));
                __nv_bfloat16 h0 = __float2bfloat16(f0), h1 = __float2bfloat16(f1);
                __nv_bfloat16 l0 = __float2bfloat16(f0 - __bfloat162float(h0));
                __nv_bfloat16 l1 = __float2bfloat16(f1 - __bfloat162float(h1));
                unsigned hw = ((unsigned)__bfloat16_as_ushort(h1) << 16) | __bfloat16_as_ushort(h0);
                unsigned lw = ((unsigned)__bfloat16_as_ushort(l1) << 16) | __bfloat16_as_ushort(l0);
                unsigned off = (unsigned)t * 128 + (((unsigned)(d0 * 2)) ^ ((unsigned)(t & 7) * 16));
                *(unsigned*)(smem + A_OFF + off) = hw;
                *(unsigned*)(smem + A_OFF + 16384 + off) = lw;
            }
        }
        __syncthreads();    // A ready, zf free

        // issue staging for chunk c+1 (overlaps with MMA(c) below)
        if (c + 1 < NCHK) {
            const int cn = c + 1;
            const uint32_t bnext = bbase[cn & 1];
            const char* sh = (const char*)(g_bswh + cn * (KK * KC));
            const char* sl = (const char*)(g_bswl + cn * (KK * KC));
            uint32_t dh = bnext + (unsigned)tid * 16;
            uint32_t dl = bnext + 32768 + (unsigned)tid * 16;
#pragma unroll
            for (int j = 0; j < 4; ++j) {
                CPASYNC16(dh + 8192u * j, sh + (tid + NTHR * j) * 16);
                CPASYNC16(dl + 8192u * j, sl + (tid + NTHR * j) * 16);
            }
#pragma unroll
            for (int p = 0; p < 4; ++p) {
                int d  = p * 16 + (tid >> 5);
                int t4 = tid & 31;
                CPASYNC16(sb + ZF_OFF + (unsigned)(d * 132 + t4 * 4) * 4,
                          zb + (size_t)(cn * KC + d) * TTOT + t4 * 4);
            }
            CPCOMMIT;
        }

        // MMA: 4 k16 steps over this 64-d chunk, 3-term split
        const uint32_t bcur = bbase[c & 1];
#pragma unroll
        for (int ks = 0; ks < 4; ++ks) {
            uint32_t ah[2][4], al[2][4];
#pragma unroll
            for (int mi = 0; mi < 2; ++mi) {
                int row = wm * 32 + mi * 16 + ((lane >> 3) & 1) * 8 + (lane & 7);
                unsigned kb = (unsigned)ks * 32 + ((lane >> 4) & 1) * 16;
                uint32_t ad = sb + A_OFF + (unsigned)row * 128 + (kb ^ ((unsigned)(row & 7) * 16));
                LDSM4(ah[mi], ad);
                LDSM4(al[mi], ad + 16384);
            }
#pragma unroll
            for (int ng = 0; ng < 4; ++ng) {
                int n = wn * 64 + ng * 16 + ((lane >> 4) & 1) * 8 + (lane & 7);
                unsigned kb = (unsigned)ks * 32 + ((lane >> 3) & 1) * 16;
                uint32_t bd = bcur + (unsigned)n * 128 + (kb ^ ((unsigned)(n & 7) * 16));
                uint32_t bh[4], bl[4];
                LDSM4(bh, bd);
                LDSM4(bl, bd + 32768);
#pragma unroll
                for (int mi = 0; mi < 2; ++mi) {
#pragma unroll
                    for (int tile = 0; tile < 2; ++tile) {
                        float* dst = acc[mi][ng * 2 + tile];
                        MMA16816(dst, ah[mi], bh[tile * 2], bh[tile * 2 + 1]);
                        MMA16816(dst, al[mi], bh[tile * 2], bh[tile * 2 + 1]);
                        MMA16816(dst, ah[mi], bl[tile * 2], bl[tile * 2 + 1]);
                    }
                }
            }
        }
    }

    // ---- epilogue: argmin over 256 codes ----
    const float* es = (const float*)(smem + ES_OFF);
    float* redv = (float*)(smem + REDV_OFF);
    int*   redk = (int*)(smem + REDK_OFF);
    float* bestv_s = (float*)(smem + BV_OFF);
    int*   bestk_s = (int*)(smem + BK_OFF);
    int*   ccnt = (int*)(smem + CC_OFF);
    int*   clst = (int*)(smem + CL_OFF);
    float* lred = (float*)(smem + LRED_OFF);

    // thread-local best per t-row j: j = mi*2 + (frag>>1)
    float bv[4];
    int   bk[4];
#pragma unroll
    for (int j = 0; j < 4; ++j) { bv[j] = 3.4e38f; bk[j] = KK; }
#pragma unroll
    for (int mi = 0; mi < 2; ++mi)
#pragma unroll
        for (int nt = 0; nt < 8; ++nt)
#pragma unroll
            for (int ci = 0; ci < 4; ++ci) {
                int code = wn * 64 + nt * 8 + (lane & 3) * 2 + (ci & 1);
                int j = mi * 2 + (ci >> 1);
                float sc = es[code] - 2.0f * acc[mi][nt][ci];
                if (sc < bv[j] || (sc == bv[j] && code < bk[j])) { bv[j] = sc; bk[j] = code; }
            }
    const unsigned FULL = 0xffffffffu;
#pragma unroll
    for (int j = 0; j < 4; ++j) {
#pragma unroll
        for (int off = 1; off < 4; off <<= 1) {
            float ov = __shfl_xor_sync(FULL, bv[j], off);
            int   ok = __shfl_xor_sync(FULL, bk[j], off);
            if (ov < bv[j] || (ov == bv[j] && ok < bk[j])) { bv[j] = ov; bk[j] = ok; }
        }
    }
    if ((lane & 3) == 0) {
#pragma unroll
        for (int j = 0; j < 4; ++j) {
            int t = wm * 32 + (j >> 1) * 16 + (lane >> 2) + (j & 1) * 8;
            redv[t * 4 + wn] = bv[j];
            redk[t * 4 + wn] = bk[j];
        }
    }
    __syncthreads();
    if (tid < TTILE) {
        float fv = redv[tid * 4];
        int   fk = redk[tid * 4];
#pragma unroll
        for (int q = 1; q < 4; ++q) {
            float v = redv[tid * 4 + q];
            int   k = redk[tid * 4 + q];
            if (v < fv || (v == fv && k < fk)) { fv = v; fk = k; }
        }
        bestv_s[tid] = fv;
        bestk_s[tid] = fk;
        ccnt[tid] = 0;
        g_idx[b * TTOT + tg + tid] = fk;
    }
    __syncthreads();

    // candidate scan (score <= best + TAU, code != best)
#pragma unroll
    for (int mi = 0; mi < 2; ++mi)
#pragma unroll
        for (int nt = 0; nt < 8; ++nt)
#pragma unroll
            for (int ci = 0; ci < 4; ++ci) {
                int code = wn * 64 + nt * 8 + (lane & 3) * 2 + (ci & 1);
                int t = wm * 32 + mi * 16 + (lane >> 2) + ((ci >> 1) ? 8 : 0);
                float sc = es[code] - 2.0f * acc[mi][nt][ci];
                if (sc <= bestv_s[t] + TAU && code != bestk_s[t]) {
                    int slot = atomicAdd(&ccnt[t], 1);
                    if (slot < 7) clst[t * 7 + slot] = code;
                }
            }
    __syncthreads();

    if (tid < TTILE && ccnt[tid] > 0) {
        int slot = atomicAdd(&g_nflag, 1);
        if (slot < MAXF) {
            g_fpt[slot] = (b << 12) | (tg + tid);
            g_fold[slot] = bestk_s[tid];
            int cnum = ccnt[tid];
            if (cnum <= 7) {
                g_fcand[slot][0] = bestk_s[tid];
#pragma unroll
                for (int j = 0; j < 7; ++j)
                    if (j < cnum) g_fcand[slot][1 + j] = clst[tid * 7 + j];
                g_fcnt[slot] = cnum + 1;
            } else {
                g_fcnt[slot] = -1;   // scan all 256
            }
        }
    }

    // loss partial: sum x2 + sum best scores
    lred[tid] = x2acc + ((tid < TTILE) ? bestv_s[tid] : 0.f);
    __syncthreads();
    for (int s = NTHR / 2; s > 0; s >>= 1) {
        if (tid < s) lred[tid] += lred[tid + s];
        __syncthreads();
    }
    if (tid == 0) g_partials[b * gridDim.x + blockIdx.x] = lred[0];
}

// ---- refine: reference-fp32-EMULATED re-decision of flagged points ----
__global__ void vq_refine(const float* __restrict__ z, const float* __restrict__ cb) {
    const unsigned FULL = 0xffffffffu;
    __shared__ float zsh[4][DD];
    const int lane = threadIdx.x & 31;
    const int warp = threadIdx.x >> 5;
    const int warps_total = gridDim.x * (blockDim.x >> 5);
    const int wg = blockIdx.x * (blockDim.x >> 5) + warp;

    int n = g_nflag;
    if (n > MAXF) n = MAXF;

    for (int e = wg; e < n; e += warps_total) {
        const int pt = g_fpt[e];
        const int b = pt >> 12;
        const int t = pt & 4095;
        const int kold = g_fold[e];
        const float* zp = z + (size_t)b * DD * TTOT + t;

        for (int d = lane; d < DD; d += 32) zsh[warp][d] = zp[(size_t)d * TTOT];
        __syncwarp();

        float s = 0.f;
#pragma unroll
        for (int j = 0; j < DD / 32; ++j) {
            float v = zsh[warp][lane + 32 * j];
            s = fmaf(v, v, s);
        }
#pragma unroll
        for (int off = 16; off; off >>= 1) s += __shfl_down_sync(FULL, s, off);
        const float x2f = __shfl_sync(FULL, s, 0);

        const int cnt = g_fcnt[e];
        const int ncand = (cnt < 0) ? KK : cnt;

        float bestdf = 3.4e38f;
        int bestk = 1 << 30;
        float dfold_l = 0.f;
        for (int c = lane; c < ncand; c += 32) {
            const int k = (cnt < 0) ? c : g_fcand[e][c];
            const float* ck = cb + (size_t)k * DD;
            float dot = 0.f;
#pragma unroll 8
            for (int d = 0; d < DD; ++d) dot = fmaf(zsh[warp][d], ck[d], dot);
            float df = __fadd_rn(__fsub_rn(x2f, 2.0f * dot), g_e2f[k]);
            if (df < bestdf || (df == bestdf && k < bestk)) { bestdf = df; bestk = k; }
            if (k == kold) dfold_l = df;
        }
#pragma unroll
        for (int off = 16; off; off >>= 1) {
            float od = __shfl_down_sync(FULL, bestdf, off);
            int   ok = __shfl_down_sync(FULL, bestk, off);
            float oo = __shfl_down_sync(FULL, dfold_l, off);
            if (od < bestdf || (od == bestdf && ok < bestk)) { bestdf = od; bestk = ok; }
            dfold_l += oo;
        }
        if (lane == 0) {
            g_idx[b * TTOT + t] = bestk;
            g_ldelta[e] = bestdf - dfold_l;
        }
        __syncwarp();
    }
}

// ---- writer: gather-only quantize + indices ----
__global__ __launch_bounds__(256) void vq_write(float* __restrict__ out) {
    const int tid = threadIdx.x;
    const int b  = blockIdx.y;
    const int dz = blockIdx.z;
    const int t4 = (blockIdx.x * 256 + tid) << 2;

    const int4 kk = *(const int4*)&g_idx[b * TTOT + t4];

    if (dz == 0) {
        float4 fi = make_float4((float)kk.x, (float)kk.y, (float)kk.z, (float)kk.w);
        *(float4*)&out[Q_ELEMS + (size_t)b * TTOT + t4] = fi;
    }

    float* ob = out + (size_t)b * DD * TTOT + t4;
    const int dlo = dz * (DD / 4);
#pragma unroll 4
    for (int d = dlo; d < dlo + DD / 4; ++d) {
        const float* row = g_ct + d * KK;
        float4 q = make_float4(row[kk.x], row[kk.y], row[kk.z], row[kk.w]);
        *(float4*)&ob[(size_t)d * TTOT] = q;
    }
}

// ---- finalize ----
__global__ void vq_finalize(float* __restrict__ out) {
    __shared__ float s[256];
    int n = g_nflag;
    if (n > MAXF) n = MAXF;
    float a = 0.f;
    for (int j = threadIdx.x; j < NPART; j += 256) a += g_partials[j];
    for (int e = threadIdx.x; e < n; e += 256) a += g_ldelta[e];
    s[threadIdx.x] = a;
    __syncthreads();
    for (int st = 128; st > 0; st >>= 1) {
        if (threadIdx.x < st) s[threadIdx.x] += s[threadIdx.x + st];
        __syncthreads();
    }
    if (threadIdx.x == 0)
        out[Q_ELEMS + IDX_ELEMS] =
            0.25f * s[0] / (float)((size_t)BB * TTOT * DD);
}

extern "C" void kernel_launch(void* const* d_in, const int* in_sizes, int n_in,
                              void* d_out, int out_size) {
    const float* z  = (const float*)d_in[0];
    const float* cb = (const float*)d_in[1];
    float* out = (float*)d_out;

    cudaFuncSetAttribute(vq_main, cudaFuncAttributeMaxDynamicSharedMemorySize, SMEM_SZ);

    vq_prep<<<801, 256>>>(cb);
    dim3 grid(TTOT / TTILE, BB);
    vq_main<<<grid, NTHR, SMEM_SZ>>>(z);
    vq_refine<<<64, 128>>>(z, cb);
    dim3 wgrid(TTOT / 1024, BB, 4);
    vq_write<<<wgrid, 256>>>(out);
    vq_finalize<<<1, 256>>>(out);
}

// round 10
// speedup vs baseline: 1.1862x; 1.0722x over previous
#include <cuda_runtime.h>
#include <cuda_bf16.h>
#include <cstdint>

// Problem constants
#define BB    32
#define DD    384
#define TTOT  4096
#define TTILE 64
#define NTHR  256
#define KK    256
#define KC    64
#define NCHK  6
#define TAU   1e-2f
#define MAXF  32768
#define NPART 2048

#define Q_ELEMS   ((size_t)BB * DD * TTOT)
#define IDX_ELEMS ((size_t)BB * TTOT)

// SMEM layout (bytes)
#define A_OFF     0        // z bf16 hi(8K)+lo(8K), rows=t(64), 128B, swizzled
#define B_OFF     16384    // cb bf16 hi(32K)+lo(32K), rows=k, 128B, swizzled
#define ES_OFF    81920    // e2 [256] f32
#define REDV_OFF  82944    // [64][4] f32
#define REDK_OFF  83968    // [64][4] i32
#define BV_OFF    84992    // [64] f32
#define BK_OFF    85248    // [64] i32
#define CC_OFF    85504    // [64] i32
#define CL_OFF    85760    // [64][7] i32
#define LRED_OFF  87552    // [256] f32
#define SMEM_SZ   88576    // occ 2 @ 256 thr

// Scratch
__device__ float  g_ct[DD * KK];
__device__ float  g_e2f[KK];
__device__ int    g_idx[BB * TTOT];
__device__ float  g_partials[NPART];
__device__ int    g_nflag;
__device__ int    g_fpt[MAXF];
__device__ int    g_fcnt[MAXF];
__device__ int    g_fold[MAXF];
__device__ int    g_fcand[MAXF][8];
__device__ float  g_ldelta[MAXF];
__device__ unsigned short g_bswh[NCHK * KK * KC];  // pre-swizzled bf16 codebook hi
__device__ unsigned short g_bswl[NCHK * KK * KC];  // lo

static __device__ __forceinline__ uint32_t smem_u32(const void* p) {
    uint32_t a;
    asm("{ .reg .u64 t; cvta.to.shared.u64 t, %1; cvt.u32.u64 %0, t; }"
        : "=r"(a) : "l"(p));
    return a;
}

#define CPASYNC16(dst, src) \
    asm volatile("cp.async.cg.shared.global [%0], [%1], 16;" \
        :: "r"(dst), "l"(src) : "memory")
#define CPCOMMIT  asm volatile("cp.async.commit_group;" ::: "memory")
#define CPWAIT0   asm volatile("cp.async.wait_group 0;" ::: "memory")

#define LDSM4(r, ad) \
    asm volatile("ldmatrix.sync.aligned.m8n8.x4.shared.b16 {%0,%1,%2,%3}, [%4];" \
        : "=r"((r)[0]), "=r"((r)[1]), "=r"((r)[2]), "=r"((r)[3]) : "r"(ad))

#define MMA16816(d, a, b0, b1) \
    asm volatile("mma.sync.aligned.m16n8k16.row.col.f32.bf16.bf16.f32 " \
        "{%0,%1,%2,%3},{%4,%5,%6,%7},{%8,%9},{%0,%1,%2,%3};" \
        : "+f"((d)[0]), "+f"((d)[1]), "+f"((d)[2]), "+f"((d)[3]) \
        : "r"((a)[0]), "r"((a)[1]), "r"((a)[2]), "r"((a)[3]), "r"(b0), "r"(b1))

// ---- prep: g_ct transpose + XLA-emulated e2 + bf16 split/swizzle codebook + reset ----
__global__ void vq_prep(const float* __restrict__ cb) {
    const unsigned FULL = 0xffffffffu;
    int bid = blockIdx.x;
    if (bid < 384) {
        int gid = bid * 256 + threadIdx.x;
        int k = gid / DD;
        int d = gid - k * DD;
        g_ct[d * KK + k] = cb[gid];
    } else if (bid < 416) {
        int lane = threadIdx.x & 31;
        int warp = threadIdx.x >> 5;
        int row = (bid - 384) * 8 + warp;
        const float* c = cb + (size_t)row * DD;
        float s = 0.f;
#pragma unroll
        for (int j = 0; j < DD / 32; ++j) {
            float v = c[lane + 32 * j];
            s = fmaf(v, v, s);
        }
#pragma unroll
        for (int off = 16; off; off >>= 1) s += __shfl_down_sync(FULL, s, off);
        if (lane == 0) g_e2f[row] = s;
    } else if (bid < 800) {
        int gid = (bid - 416) * 256 + threadIdx.x;   // < 98304
        int k = gid / DD;
        int d = gid - k * DD;
        float x = cb[gid];
        __nv_bfloat16 h = __float2bfloat16(x);
        __nv_bfloat16 l = __float2bfloat16(x - __bfloat162float(h));
        int c   = d >> 6;
        int din = d & 63;
        int idx16 = c * (KK * KC) + k * KC
                  + ((((unsigned)(din * 2)) ^ ((unsigned)(k & 7) * 16)) >> 1);
        g_bswh[idx16] = __bfloat16_as_ushort(h);
        g_bswl[idx16] = __bfloat16_as_ushort(l);
    } else {
        if (threadIdx.x == 0) g_nflag = 0;
    }
}

// ---- main: mma.sync bf16-split screening, occ-2 + reg-prefetched z ----
__global__ __launch_bounds__(NTHR, 2) void vq_main(const float* __restrict__ z) {
    extern __shared__ char smem[];
    const uint32_t sb = smem_u32(smem);
    const int tid  = threadIdx.x;
    const int lane = tid & 31;
    const int w    = tid >> 5;
    const int wm   = w & 1;    // t slice (32 t)
    const int wn   = w >> 1;   // code slice (64 codes)
    const int b    = blockIdx.y;
    const int tg   = blockIdx.x * TTILE;

    ((float*)(smem + ES_OFF))[tid] = g_e2f[tid];

    const float* zb = z + (size_t)b * DD * TTOT + tg;
    const int zt = tid & 63;     // this thread's t for z staging
    const int zdg = tid >> 6;    // d-group (0..3), 16 d each

    float acc[2][8][4];   // [mi][n8 tile][frag]
#pragma unroll
    for (int i = 0; i < 2; ++i)
#pragma unroll
        for (int j = 0; j < 8; ++j)
#pragma unroll
            for (int q = 0; q < 4; ++q) acc[i][j][q] = 0.f;

    float x2acc = 0.f;
    float zr[16];

    // prologue: issue B(0) cp.async, prefetch z(0) into registers
    {
        const char* sh = (const char*)(g_bswh);
        const char* sl = (const char*)(g_bswl);
        uint32_t dh = sb + B_OFF + (unsigned)tid * 16;
        uint32_t dl = sb + B_OFF + 32768 + (unsigned)tid * 16;
#pragma unroll
        for (int j = 0; j < 8; ++j) {
            CPASYNC16(dh + 4096u * j, sh + (tid + NTHR * j) * 16);
            CPASYNC16(dl + 4096u * j, sl + (tid + NTHR * j) * 16);
        }
        CPCOMMIT;
#pragma unroll
        for (int j = 0; j < 16; ++j)
            zr[j] = zb[(size_t)(zdg * 16 + j) * TTOT + zt];
    }

    for (int c = 0; c < NCHK; ++c) {
        __syncthreads();    // MMA(c-1) done reading A and B
        // issue B(c) staging for c>0 (B buffer now free); overlaps convert below
        if (c > 0) {
            const char* sh = (const char*)(g_bswh + c * (KK * KC));
            const char* sl = (const char*)(g_bswl + c * (KK * KC));
            uint32_t dh = sb + B_OFF + (unsigned)tid * 16;
            uint32_t dl = sb + B_OFF + 32768 + (unsigned)tid * 16;
#pragma unroll
            for (int j = 0; j < 8; ++j) {
                CPASYNC16(dh + 4096u * j, sh + (tid + NTHR * j) * 16);
                CPASYNC16(dl + 4096u * j, sl + (tid + NTHR * j) * 16);
            }
            CPCOMMIT;
        }

        // convert zr(c) -> A tile (rows=t, bf16 hi/lo pairs along d, swizzled) + x2
#pragma unroll
        for (int m = 0; m < 8; ++m) {
            int d0 = zdg * 16 + 2 * m;
            float f0 = zr[2 * m];
            float f1 = zr[2 * m + 1];
            x2acc = fmaf(f0, f0, fmaf(f1, f1, x2acc));
            __nv_bfloat16 h0 = __float2bfloat16(f0), h1 = __float2bfloat16(f1);
            __nv_bfloat16 l0 = __float2bfloat16(f0 - __bfloat162float(h0));
            __nv_bfloat16 l1 = __float2bfloat16(f1 - __bfloat162float(h1));
            unsigned hw = ((unsigned)__bfloat16_as_ushort(h1) << 16) | __bfloat16_as_ushort(h0);
            unsigned lw = ((unsigned)__bfloat16_as_ushort(l1) << 16) | __bfloat16_as_ushort(l0);
            unsigned off = (unsigned)zt * 128 + (((unsigned)(d0 * 2)) ^ ((unsigned)(zt & 7) * 16));
            *(unsigned*)(smem + A_OFF + off) = hw;
            *(unsigned*)(smem + A_OFF + 8192 + off) = lw;
        }

        // prefetch z(c+1) into registers (latency hides under MMA(c))
        if (c + 1 < NCHK) {
#pragma unroll
            for (int j = 0; j < 16; ++j)
                zr[j] = zb[(size_t)((c + 1) * KC + zdg * 16 + j) * TTOT + zt];
        }

        CPWAIT0;            // B(c) staged
        __syncthreads();    // A + B visible to all warps

        // MMA: 4 k16 steps over this 64-d chunk, 3-term split
#pragma unroll
        for (int ks = 0; ks < 4; ++ks) {
            uint32_t ah[2][4], al[2][4];
#pragma unroll
            for (int mi = 0; mi < 2; ++mi) {
                int row = wm * 32 + mi * 16 + ((lane >> 3) & 1) * 8 + (lane & 7);
                unsigned kb = (unsigned)ks * 32 + ((lane >> 4) & 1) * 16;
                uint32_t ad = sb + A_OFF + (unsigned)row * 128 + (kb ^ ((unsigned)(row & 7) * 16));
                LDSM4(ah[mi], ad);
                LDSM4(al[mi], ad + 8192);
            }
#pragma unroll
            for (int ng = 0; ng < 4; ++ng) {
                int n = wn * 64 + ng * 16 + ((lane >> 4) & 1) * 8 + (lane & 7);
                unsigned kb = (unsigned)ks * 32 + ((lane >> 3) & 1) * 16;
                uint32_t bd = sb + B_OFF + (unsigned)n * 128 + (kb ^ ((unsigned)(n & 7) * 16));
                uint32_t bh[4], bl[4];
                LDSM4(bh, bd);
                LDSM4(bl, bd + 32768);
#pragma unroll
                for (int mi = 0; mi < 2; ++mi) {
#pragma unroll
                    for (int tile = 0; tile < 2; ++tile) {
                        float* dst = acc[mi][ng * 2 + tile];
                        MMA16816(dst, ah[mi], bh[tile * 2], bh[tile * 2 + 1]);
                        MMA16816(dst, al[mi], bh[tile * 2], bh[tile * 2 + 1]);
                        MMA16816(dst, ah[mi], bl[tile * 2], bl[tile * 2 + 1]);
                    }
                }
            }
        }
    }

    // ---- epilogue: argmin over 256 codes ----
    const float* es = (const float*)(smem + ES_OFF);
    float* redv = (float*)(smem + REDV_OFF);
    int*   redk = (int*)(smem + REDK_OFF);
    float* bestv_s = (float*)(smem + BV_OFF);
    int*   bestk_s = (int*)(smem + BK_OFF);
    int*   ccnt = (int*)(smem + CC_OFF);
    int*   clst = (int*)(smem + CL_OFF);
    float* lred = (float*)(smem + LRED_OFF);

    float bv[4];
    int   bk[4];
#pragma unroll
    for (int j = 0; j < 4; ++j) { bv[j] = 3.4e38f; bk[j] = KK; }
#pragma unroll
    for (int mi = 0; mi < 2; ++mi)
#pragma unroll
        for (int nt = 0; nt < 8; ++nt)
#pragma unroll
            for (int ci = 0; ci < 4; ++ci) {
                int code = wn * 64 + nt * 8 + (lane & 3) * 2 + (ci & 1);
                int j = mi * 2 + (ci >> 1);
                float sc = es[code] - 2.0f * acc[mi][nt][ci];
                if (sc < bv[j] || (sc == bv[j] && code < bk[j])) { bv[j] = sc; bk[j] = code; }
            }
    const unsigned FULL = 0xffffffffu;
#pragma unroll
    for (int j = 0; j < 4; ++j) {
#pragma unroll
        for (int off = 1; off < 4; off <<= 1) {
            float ov = __shfl_xor_sync(FULL, bv[j], off);
            int   ok = __shfl_xor_sync(FULL, bk[j], off);
            if (ov < bv[j] || (ov == bv[j] && ok < bk[j])) { bv[j] = ov; bk[j] = ok; }
        }
    }
    if ((lane & 3) == 0) {
#pragma unroll
        for (int j = 0; j < 4; ++j) {
            int t = wm * 32 + (j >> 1) * 16 + (lane >> 2) + (j & 1) * 8;
            redv[t * 4 + wn] = bv[j];
            redk[t * 4 + wn] = bk[j];
        }
    }
    __syncthreads();
    if (tid < TTILE) {
        float fv = redv[tid * 4];
        int   fk = redk[tid * 4];
#pragma unroll
        for (int q = 1; q < 4; ++q) {
            float v = redv[tid * 4 + q];
            int   k = redk[tid * 4 + q];
            if (v < fv || (v == fv && k < fk)) { fv = v; fk = k; }
        }
        bestv_s[tid] = fv;
        bestk_s[tid] = fk;
        ccnt[tid] = 0;
        g_idx[b * TTOT + tg + tid] = fk;
    }
    __syncthreads();

    // candidate scan (score <= best + TAU, code != best)
#pragma unroll
    for (int mi = 0; mi < 2; ++mi)
#pragma unroll
        for (int nt = 0; nt < 8; ++nt)
#pragma unroll
            for (int ci = 0; ci < 4; ++ci) {
                int code = wn * 64 + nt * 8 + (lane & 3) * 2 + (ci & 1);
                int t = wm * 32 + mi * 16 + (lane >> 2) + ((ci >> 1) ? 8 : 0);
                float sc = es[code] - 2.0f * acc[mi][nt][ci];
                if (sc <= bestv_s[t] + TAU && code != bestk_s[t]) {
                    int slot = atomicAdd(&ccnt[t], 1);
                    if (slot < 7) clst[t * 7 + slot] = code;
                }
            }
    __syncthreads();

    if (tid < TTILE && ccnt[tid] > 0) {
        int slot = atomicAdd(&g_nflag, 1);
        if (slot < MAXF) {
            g_fpt[slot] = (b << 12) | (tg + tid);
            g_fold[slot] = bestk_s[tid];
            int cnum = ccnt[tid];
            if (cnum <= 7) {
                g_fcand[slot][0] = bestk_s[tid];
#pragma unroll
                for (int j = 0; j < 7; ++j)
                    if (j < cnum) g_fcand[slot][1 + j] = clst[tid * 7 + j];
                g_fcnt[slot] = cnum + 1;
            } else {
                g_fcnt[slot] = -1;   // scan all 256
            }
        }
    }

    // loss partial: sum x2 + sum best scores
    lred[tid] = x2acc + ((tid < TTILE) ? bestv_s[tid] : 0.f);
    __syncthreads();
    for (int s = NTHR / 2; s > 0; s >>= 1) {
        if (tid < s) lred[tid] += lred[tid + s];
        __syncthreads();
    }
    if (tid == 0) g_partials[b * gridDim.x + blockIdx.x] = lred[0];
}

// ---- refine: reference-fp32-EMULATED re-decision of flagged points ----
__global__ void vq_refine(const float* __restrict__ z, const float* __restrict__ cb) {
    const unsigned FULL = 0xffffffffu;
    __shared__ float zsh[4][DD];
    const int lane = threadIdx.x & 31;
    const int warp = threadIdx.x >> 5;
    const int warps_total = gridDim.x * (blockDim.x >> 5);
    const int wg = blockIdx.x * (blockDim.x >> 5) + warp;

    int n = g_nflag;
    if (n > MAXF) n = MAXF;

    for (int e = wg; e < n; e += warps_total) {
        const int pt = g_fpt[e];
        const int b = pt >> 12;
        const int t = pt & 4095;
        const int kold = g_fold[e];
        const float* zp = z + (size_t)b * DD * TTOT + t;

        for (int d = lane; d < DD; d += 32) zsh[warp][d] = zp[(size_t)d * TTOT];
        __syncwarp();

        float s = 0.f;
#pragma unroll
        for (int j = 0; j < DD / 32; ++j) {
            float v = zsh[warp][lane + 32 * j];
            s = fmaf(v, v, s);
        }
#pragma unroll
        for (int off = 16; off; off >>= 1) s += __shfl_down_sync(FULL, s, off);
        const float x2f = __shfl_sync(FULL, s, 0);

        const int cnt = g_fcnt[e];
        const int ncand = (cnt < 0) ? KK : cnt;

        float bestdf = 3.4e38f;
        int bestk = 1 << 30;
        float dfold_l = 0.f;
        for (int c = lane; c < ncand; c += 32) {
            const int k = (cnt < 0) ? c : g_fcand[e][c];
            const float* ck = cb + (size_t)k * DD;
            float dot = 0.f;
#pragma unroll 8
            for (int d = 0; d < DD; ++d) dot = fmaf(zsh[warp][d], ck[d], dot);
            float df = __fadd_rn(__fsub_rn(x2f, 2.0f * dot), g_e2f[k]);
            if (df < bestdf || (df == bestdf && k < bestk)) { bestdf = df; bestk = k; }
            if (k == kold) dfold_l = df;
        }
#pragma unroll
        for (int off = 16; off; off >>= 1) {
            float od = __shfl_down_sync(FULL, bestdf, off);
            int   ok = __shfl_down_sync(FULL, bestk, off);
            float oo = __shfl_down_sync(FULL, dfold_l, off);
            if (od < bestdf || (od == bestdf && ok < bestk)) { bestdf = od; bestk = ok; }
            dfold_l += oo;
        }
        if (lane == 0) {
            g_idx[b * TTOT + t] = bestk;
            g_ldelta[e] = bestdf - dfold_l;
        }
        __syncwarp();
    }
}

// ---- writer: gather-only quantize + indices ----
__global__ __launch_bounds__(256) void vq_write(float* __restrict__ out) {
    const int tid = threadIdx.x;
    const int b  = blockIdx.y;
    const int dz = blockIdx.z;                      // 0..7, 48 d each
    const int t4 = (blockIdx.x * 256 + tid) << 2;

    const int4 kk = *(const int4*)&g_idx[b * TTOT + t4];

    if (dz == 0) {
        float4 fi = make_float4((float)kk.x, (float)kk.y, (float)kk.z, (float)kk.w);
        *(float4*)&out[Q_ELEMS + (size_t)b * TTOT + t4] = fi;
    }

    float* ob = out + (size_t)b * DD * TTOT + t4;
    const int dlo = dz * (DD / 8);
#pragma unroll 4
    for (int d = dlo; d < dlo + DD / 8; ++d) {
        const float* row = g_ct + d * KK;
        float4 q = make_float4(row[kk.x], row[kk.y], row[kk.z], row[kk.w]);
        *(float4*)&ob[(size_t)d * TTOT] = q;
    }
}

// ---- finalize ----
__global__ void vq_finalize(float* __restrict__ out) {
    __shared__ float s[256];
    int n = g_nflag;
    if (n > MAXF) n = MAXF;
    float a = 0.f;
    for (int j = threadIdx.x; j < NPART; j += 256) a += g_partials[j];
    for (int e = threadIdx.x; e < n; e += 256) a += g_ldelta[e];
    s[threadIdx.x] = a;
    __syncthreads();
    for (int st = 128; st > 0; st >>= 1) {
        if (threadIdx.x < st) s[threadIdx.x] += s[threadIdx.x + st];
        __syncthreads();
    }
    if (threadIdx.x == 0)
        out[Q_ELEMS + IDX_ELEMS] =
            0.25f * s[0] / (float)((size_t)BB * TTOT * DD);
}

extern "C" void kernel_launch(void* const* d_in, const int* in_sizes, int n_in,
                              void* d_out, int out_size) {
    const float* z  = (const float*)d_in[0];
    const float* cb = (const float*)d_in[1];
    float* out = (float*)d_out;

    cudaFuncSetAttribute(vq_main, cudaFuncAttributeMaxDynamicSharedMemorySize, SMEM_SZ);

    vq_prep<<<801, 256>>>(cb);
    dim3 grid(TTOT / TTILE, BB);
    vq_main<<<grid, NTHR, SMEM_SZ>>>(z);
    vq_refine<<<64, 128>>>(z, cb);
    dim3 wgrid(TTOT / 1024, BB, 8);
    vq_write<<<wgrid, 256>>>(out);
    vq_finalize<<<1, 256>>>(out);
}